// round 14
// baseline (speedup 1.0000x reference)
#include <cuda_runtime.h>
#include <math.h>

// StatefulSynapseNet, R14: R13 body exactly (dual-sample warp, const-port
// weights, f32x2 FFMA GEMMs in two o-halves, pitch-33 transposes, deferred
// synapse filter in the 20-lane final scan) with block shape 3 warps / 96
// threads + __launch_bounds__(96,10): 10 blocks/SM -> 30 warps (occ ~47%).

typedef unsigned long long ull;

__device__ __forceinline__ ull pack2(float lo, float hi) {
    ull r; asm("mov.b64 %0, {%1,%2};" : "=l"(r) : "f"(lo), "f"(hi)); return r;
}
__device__ __forceinline__ void unpack2(ull v, float& lo, float& hi) {
    asm("mov.b64 {%0,%1}, %2;" : "=f"(lo), "=f"(hi) : "l"(v));
}
__device__ __forceinline__ ull ffma2(ull a, ull b, ull c) {
    ull d; asm("fma.rn.f32x2 %0, %1, %2, %3;" : "=l"(d) : "l"(a), "l"(b), "l"(c)); return d;
}
__device__ __forceinline__ float set_ge(float a, float b) {
    float d; asm("set.ge.f32.f32 %0, %1, %2;" : "=f"(d) : "f"(a), "f"(b)); return d;
}

#define T_DIM 28
#define F_DIM 28
#define C1 32
#define C2 10
#define WARPS 3            // 96-thread blocks -> 22.3KB smem -> 10 blocks/SM
#define SPW 2
#define HP 33              // H/s pitch, conflict-free scalar pattern (proven)
#define H2P 29             // z buffer pitch (overlays dead H region)
#define REGION 928         // 28*33 = 924 floats, padded to 16B multiple

// constant-block layout (floats) — identical to R6/R8/R10/R13
#define OFF_W1T 0          // [f*32 + o] = W1[o*28+f]
#define OFF_W2  896        // [j*32 + o]
#define OFF_B1  1216
#define OFF_B2  1248
#define OFF_ITAU 1258
#define CP_SIZE 1280

__constant__ __align__(16) float c_P[CP_SIZE];
__device__   __align__(16) float g_stage[CP_SIZE];

__global__ void setup_kernel(const float* __restrict__ W1,
                             const float* __restrict__ b1,
                             const float* __restrict__ w_syn,
                             const float* __restrict__ W2,
                             const float* __restrict__ b2)
{
    int i = threadIdx.x;
    for (int idx = i; idx < C1 * F_DIM; idx += 1024) {
        int f = idx >> 5, o = idx & 31;
        g_stage[OFF_W1T + idx] = W1[o * F_DIM + f];
    }
    for (int idx = i; idx < C2 * C1; idx += 1024)
        g_stage[OFF_W2 + idx] = W2[idx];
    if (i < C1) g_stage[OFF_B1 + i] = b1[i];
    if (i < C2) g_stage[OFF_B2 + i] = b2[i];
    if (i == 0) g_stage[OFF_ITAU] = 1.0f / (1.0f + expf(-w_syn[0]));
}

__global__ __launch_bounds__(WARPS * 32, 10)
void snn_kernel(const float* __restrict__ x, float* __restrict__ out, int N)
{
    __shared__ float sh[WARPS * SPW * REGION];
    const int lane = threadIdx.x & 31;
    const int warp = threadIdx.x >> 5;
    const int n0 = (blockIdx.x * WARPS + warp) * SPW;
    if (n0 >= N) return;
    const bool has_b = (n0 + 1 < N);
    const int n1 = has_b ? (n0 + 1) : n0;

    float* shA = sh + warp * (SPW * REGION);   // H/s [t][o] pitch 33; z overlays
    float* shB = shA + REGION;
    const bool tl = (lane < T_DIM);
    const int t_eff = tl ? lane : (T_DIM - 1); // clamp: x loads unconditional

    const float* xa = x + (size_t)n0 * (F_DIM * T_DIM) + t_eff;
    const float* xb = x + (size_t)n1 * (F_DIM * T_DIM) + t_eff;

    // ---- phase 1: lane = t, two o-halves; acc = 8 ull per sample per half ----
#pragma unroll
    for (int half = 0; half < 2; ++half) {
        ull accA[8], accB[8];
#pragma unroll
        for (int p = 0; p < 8; ++p) {
            ull b = *reinterpret_cast<const ull*>(c_P + OFF_B1 + half * 16 + 2 * p);
            accA[p] = b; accB[p] = b;
        }
#pragma unroll 7
        for (int f = 0; f < F_DIM; ++f) {
            float xva = __ldg(xa + f * T_DIM);           // in-bounds (clamped base)
            float xvb = __ldg(xb + f * T_DIM);
            ull xpa = pack2(xva, xva);
            ull xpb = pack2(xvb, xvb);
            const ulonglong2* wq =
                reinterpret_cast<const ulonglong2*>(c_P + OFF_W1T + f * C1 + half * 16);
#pragma unroll
            for (int q = 0; q < 4; ++q) {                // each const load feeds 4 FFMA2
                ulonglong2 w = wq[q];
                accA[2 * q]     = ffma2(xpa, w.x, accA[2 * q]);
                accB[2 * q]     = ffma2(xpb, w.x, accB[2 * q]);
                accA[2 * q + 1] = ffma2(xpa, w.y, accA[2 * q + 1]);
                accB[2 * q + 1] = ffma2(xpb, w.y, accB[2 * q + 1]);
            }
        }
        if (tl) {
#pragma unroll
            for (int p = 0; p < 8; ++p) {
                float a0, a1, b0, b1v;
                unpack2(accA[p], a0, a1);
                unpack2(accB[p], b0, b1v);
                shA[lane * HP + half * 16 + 2 * p]     = a0;
                shA[lane * HP + half * 16 + 2 * p + 1] = a1;
                shB[lane * HP + half * 16 + 2 * p]     = b0;
                shB[lane * HP + half * 16 + 2 * p + 1] = b1v;
            }
        }
    }
    __syncwarp();

    // ---- IF scan (lane = o): spike + reset ONLY; write s floats in place ----
    {
        float va = 0.0f, vb = 0.0f;
#pragma unroll
        for (int t = 0; t < T_DIM; ++t) {
            float ha = shA[t * HP + lane];
            float hb = shB[t * HP + lane];
            va += ha;                             vb += hb;
            float sa = set_ge(va, 1.0f);          float sb = set_ge(vb, 1.0f);
            va = fmaf(va, -sa, va);               vb = fmaf(vb, -sb, vb);   // exact reset
            shA[t * HP + lane] = sa;              // s[t][o] (filter deferred)
            shB[t * HP + lane] = sb;
        }
    }
    __syncwarp();

    // ---- phase 2: lane = t, two o-halves; z[j][t] = sum_o W2[j][o]*s[t][o] ----
    {
        float pA[C2], pB[C2];
#pragma unroll
        for (int j = 0; j < C2; ++j) { pA[j] = 0.0f; pB[j] = 0.0f; }

        if (tl) {
#pragma unroll
            for (int half = 0; half < 2; ++half) {
                ull yqa[8], yqb[8];
                const float* ya = shA + lane * HP + half * 16;
                const float* yb = shB + lane * HP + half * 16;
#pragma unroll
                for (int q = 0; q < 8; ++q) {
                    yqa[q] = pack2(ya[2 * q], ya[2 * q + 1]);
                    yqb[q] = pack2(yb[2 * q], yb[2 * q + 1]);
                }
#pragma unroll
                for (int j = 0; j < C2; ++j) {
                    ull a2 = 0ULL, b2a = 0ULL;
                    const ulonglong2* wq2 =
                        reinterpret_cast<const ulonglong2*>(c_P + OFF_W2 + j * C1 + half * 16);
#pragma unroll
                    for (int q = 0; q < 4; ++q) {
                        ulonglong2 w = wq2[q];
                        a2  = ffma2(yqa[2 * q],     w.x, a2);
                        b2a = ffma2(yqb[2 * q],     w.x, b2a);
                        a2  = ffma2(yqa[2 * q + 1], w.y, a2);
                        b2a = ffma2(yqb[2 * q + 1], w.y, b2a);
                    }
                    float u0, u1, v0, v1;
                    unpack2(a2, u0, u1);
                    unpack2(b2a, v0, v1);
                    pA[j] += u0 + u1;
                    pB[j] += v0 + v1;
                }
            }
        }
        __syncwarp();                          // all s reads done -> overlay z

        if (tl) {
#pragma unroll
            for (int j = 0; j < C2; ++j) {
                shA[j * H2P + lane] = pA[j];   // z[j][t], b2 folded into final scan
                shB[j * H2P + lane] = pB[j];
            }
        }
    }
    __syncwarp();

    // ---- final scan (20 lanes): u recurrence (synapse filter) + IF + mean ----
    {
        int sj = lane & 15;
        int ss = lane >> 4;
        if (sj < C2 && (ss == 0 || has_b)) {
            const float* z = ss ? shB : shA;
            const float itau = c_P[OFF_ITAU];
            const float bj = c_P[OFF_B2 + sj];
            float u = 0.0f, v = 0.0f, cnt = 0.0f;
#pragma unroll
            for (int t = 0; t < T_DIM; ++t) {
                u = fmaf(u, -itau, u) + z[sj * H2P + t];   // u = u - u*itau + z
                v += u + bj;                               // h2 = u + b2
                float s = set_ge(v, 1.0f);
                cnt += s;
                v = fmaf(v, -s, v);                        // exact reset
            }
            int nn = ss ? n1 : n0;
            out[(size_t)nn * C2 + sj] = cnt * (1.0f / 28.0f);
        }
    }
}

extern "C" void kernel_launch(void* const* d_in, const int* in_sizes, int n_in,
                              void* d_out, int out_size)
{
    const float* x     = (const float*)d_in[0];
    const float* W1    = (const float*)d_in[1];
    const float* b1    = (const float*)d_in[2];
    const float* w_syn = (const float*)d_in[3];
    const float* W2    = (const float*)d_in[4];
    const float* b2    = (const float*)d_in[5];
    float* out = (float*)d_out;

    const int N = in_sizes[0] / (F_DIM * T_DIM);

    setup_kernel<<<1, 1024>>>(W1, b1, w_syn, W2, b2);

    void* sp = nullptr;
    cudaGetSymbolAddress(&sp, g_stage);
    cudaMemcpyToSymbolAsync(c_P, sp, CP_SIZE * sizeof(float), 0,
                            cudaMemcpyDeviceToDevice, 0);

    const int spb = WARPS * SPW;
    const int blocks = (N + spb - 1) / spb;
    snn_kernel<<<blocks, WARPS * 32>>>(x, out, N);
}

// round 15
// speedup vs baseline: 1.0222x; 1.0222x over previous
#include <cuda_runtime.h>
#include <math.h>

// StatefulSynapseNet, R15: R13 exactly (dual-sample warp, const-port weights,
// f32x2 FFMA GEMMs in two o-halves, deferred synapse filter) but with the
// H/s buffer at even pitch 34 so the phase-1 transpose stores packed accs
// directly (STS.64) and phase-2 reads y as LDS.64 — removing ~160 pack/unpack
// /scalar-LDS-STS instructions per pair. Register target left at 7 blocks
// (the R5 experiment confounded this layout with a forced 48-reg cap).

typedef unsigned long long ull;

__device__ __forceinline__ ull pack2(float lo, float hi) {
    ull r; asm("mov.b64 %0, {%1,%2};" : "=l"(r) : "f"(lo), "f"(hi)); return r;
}
__device__ __forceinline__ void unpack2(ull v, float& lo, float& hi) {
    asm("mov.b64 {%0,%1}, %2;" : "=f"(lo), "=f"(hi) : "l"(v));
}
__device__ __forceinline__ ull ffma2(ull a, ull b, ull c) {
    ull d; asm("fma.rn.f32x2 %0, %1, %2, %3;" : "=l"(d) : "l"(a), "l"(b), "l"(c)); return d;
}
__device__ __forceinline__ float set_ge(float a, float b) {
    float d; asm("set.ge.f32.f32 %0, %1, %2;" : "=f"(d) : "f"(a), "f"(b)); return d;
}

#define T_DIM 28
#define F_DIM 28
#define C1 32
#define C2 10
#define WARPS 4
#define SPW 2
#define HP 34              // even pitch: 8B-aligned rows, word-stride 17 (odd) ->
                           // row LDS.64/STS.64 conflict-free; column scalar
                           // bank = (2t+lane)%32 also conflict-free
#define H2P 29             // z buffer pitch (overlays dead H region)
#define REGION 952         // 28*34 floats (3808 B, 16B multiple)

// constant-block layout (floats) — identical to R6/R8/R10/R13
#define OFF_W1T 0          // [f*32 + o] = W1[o*28+f]
#define OFF_W2  896        // [j*32 + o]
#define OFF_B1  1216
#define OFF_B2  1248
#define OFF_ITAU 1258
#define CP_SIZE 1280

__constant__ __align__(16) float c_P[CP_SIZE];
__device__   __align__(16) float g_stage[CP_SIZE];

__global__ void setup_kernel(const float* __restrict__ W1,
                             const float* __restrict__ b1,
                             const float* __restrict__ w_syn,
                             const float* __restrict__ W2,
                             const float* __restrict__ b2)
{
    int i = threadIdx.x;
    for (int idx = i; idx < C1 * F_DIM; idx += 1024) {
        int f = idx >> 5, o = idx & 31;
        g_stage[OFF_W1T + idx] = W1[o * F_DIM + f];
    }
    for (int idx = i; idx < C2 * C1; idx += 1024)
        g_stage[OFF_W2 + idx] = W2[idx];
    if (i < C1) g_stage[OFF_B1 + i] = b1[i];
    if (i < C2) g_stage[OFF_B2 + i] = b2[i];
    if (i == 0) g_stage[OFF_ITAU] = 1.0f / (1.0f + expf(-w_syn[0]));
}

__global__ __launch_bounds__(WARPS * 32, 7)
void snn_kernel(const float* __restrict__ x, float* __restrict__ out, int N)
{
    __shared__ float sh[WARPS * SPW * REGION];
    const int lane = threadIdx.x & 31;
    const int warp = threadIdx.x >> 5;
    const int n0 = (blockIdx.x * WARPS + warp) * SPW;
    if (n0 >= N) return;
    const bool has_b = (n0 + 1 < N);
    const int n1 = has_b ? (n0 + 1) : n0;

    float* shA = sh + warp * (SPW * REGION);   // H/s [t][o] pitch 34; z overlays
    float* shB = shA + REGION;
    const bool tl = (lane < T_DIM);
    const int t_eff = tl ? lane : (T_DIM - 1); // clamp: x loads unconditional

    const float* xa = x + (size_t)n0 * (F_DIM * T_DIM) + t_eff;
    const float* xb = x + (size_t)n1 * (F_DIM * T_DIM) + t_eff;

    // ---- phase 1: lane = t, two o-halves; packed accs stored via STS.64 ----
#pragma unroll
    for (int half = 0; half < 2; ++half) {
        ull accA[8], accB[8];
#pragma unroll
        for (int p = 0; p < 8; ++p) {
            ull b = *reinterpret_cast<const ull*>(c_P + OFF_B1 + half * 16 + 2 * p);
            accA[p] = b; accB[p] = b;
        }
#pragma unroll 7
        for (int f = 0; f < F_DIM; ++f) {
            float xva = __ldg(xa + f * T_DIM);           // in-bounds (clamped base)
            float xvb = __ldg(xb + f * T_DIM);
            ull xpa = pack2(xva, xva);
            ull xpb = pack2(xvb, xvb);
            const ulonglong2* wq =
                reinterpret_cast<const ulonglong2*>(c_P + OFF_W1T + f * C1 + half * 16);
#pragma unroll
            for (int q = 0; q < 4; ++q) {                // each const load feeds 4 FFMA2
                ulonglong2 w = wq[q];
                accA[2 * q]     = ffma2(xpa, w.x, accA[2 * q]);
                accB[2 * q]     = ffma2(xpb, w.x, accB[2 * q]);
                accA[2 * q + 1] = ffma2(xpa, w.y, accA[2 * q + 1]);
                accB[2 * q + 1] = ffma2(xpb, w.y, accB[2 * q + 1]);
            }
        }
        if (tl) {                                        // 8 STS.64 per sample/half
            ull* ra = reinterpret_cast<ull*>(shA + lane * HP);
            ull* rb = reinterpret_cast<ull*>(shB + lane * HP);
#pragma unroll
            for (int p = 0; p < 8; ++p) {
                ra[half * 8 + p] = accA[p];
                rb[half * 8 + p] = accB[p];
            }
        }
    }
    __syncwarp();

    // ---- IF scan (lane = o): spike + reset ONLY; s floats written in place ----
    {
        float va = 0.0f, vb = 0.0f;
#pragma unroll
        for (int t = 0; t < T_DIM; ++t) {
            float ha = shA[t * HP + lane];               // bank (2t+lane)%32, cf
            float hb = shB[t * HP + lane];
            va += ha;                             vb += hb;
            float sa = set_ge(va, 1.0f);          float sb = set_ge(vb, 1.0f);
            va = fmaf(va, -sa, va);               vb = fmaf(vb, -sb, vb);   // exact reset
            shA[t * HP + lane] = sa;              // s[t][o] (filter deferred)
            shB[t * HP + lane] = sb;
        }
    }
    __syncwarp();

    // ---- phase 2: lane = t; y read as LDS.64 pairs (ready FFMA2 operands) ----
    {
        float pA[C2], pB[C2];
#pragma unroll
        for (int j = 0; j < C2; ++j) { pA[j] = 0.0f; pB[j] = 0.0f; }

        if (tl) {
            const ull* ra = reinterpret_cast<const ull*>(shA + lane * HP);
            const ull* rb = reinterpret_cast<const ull*>(shB + lane * HP);
#pragma unroll
            for (int half = 0; half < 2; ++half) {
                ull yqa[8], yqb[8];
#pragma unroll
                for (int q = 0; q < 8; ++q) {            // 8 LDS.64 per sample/half
                    yqa[q] = ra[half * 8 + q];
                    yqb[q] = rb[half * 8 + q];
                }
#pragma unroll
                for (int j = 0; j < C2; ++j) {
                    ull a2 = 0ULL, b2a = 0ULL;
                    const ulonglong2* wq2 =
                        reinterpret_cast<const ulonglong2*>(c_P + OFF_W2 + j * C1 + half * 16);
#pragma unroll
                    for (int q = 0; q < 4; ++q) {
                        ulonglong2 w = wq2[q];
                        a2  = ffma2(yqa[2 * q],     w.x, a2);
                        b2a = ffma2(yqb[2 * q],     w.x, b2a);
                        a2  = ffma2(yqa[2 * q + 1], w.y, a2);
                        b2a = ffma2(yqb[2 * q + 1], w.y, b2a);
                    }
                    float u0, u1, v0, v1;
                    unpack2(a2, u0, u1);
                    unpack2(b2a, v0, v1);
                    pA[j] += u0 + u1;
                    pB[j] += v0 + v1;
                }
            }
        }
        __syncwarp();                          // all s reads done -> overlay z

        if (tl) {
#pragma unroll
            for (int j = 0; j < C2; ++j) {
                shA[j * H2P + lane] = pA[j];   // z[j][t], b2 folded into final scan
                shB[j * H2P + lane] = pB[j];
            }
        }
    }
    __syncwarp();

    // ---- final scan (20 lanes): u recurrence (synapse filter) + IF + mean ----
    {
        int sj = lane & 15;
        int ss = lane >> 4;
        if (sj < C2 && (ss == 0 || has_b)) {
            const float* z = ss ? shB : shA;
            const float itau = c_P[OFF_ITAU];
            const float bj = c_P[OFF_B2 + sj];
            float u = 0.0f, v = 0.0f, cnt = 0.0f;
#pragma unroll
            for (int t = 0; t < T_DIM; ++t) {
                u = fmaf(u, -itau, u) + z[sj * H2P + t];   // u = u - u*itau + z
                v += u + bj;                               // h2 = u + b2
                float s = set_ge(v, 1.0f);
                cnt += s;
                v = fmaf(v, -s, v);                        // exact reset
            }
            int nn = ss ? n1 : n0;
            out[(size_t)nn * C2 + sj] = cnt * (1.0f / 28.0f);
        }
    }
}

extern "C" void kernel_launch(void* const* d_in, const int* in_sizes, int n_in,
                              void* d_out, int out_size)
{
    const float* x     = (const float*)d_in[0];
    const float* W1    = (const float*)d_in[1];
    const float* b1    = (const float*)d_in[2];
    const float* w_syn = (const float*)d_in[3];
    const float* W2    = (const float*)d_in[4];
    const float* b2    = (const float*)d_in[5];
    float* out = (float*)d_out;

    const int N = in_sizes[0] / (F_DIM * T_DIM);

    setup_kernel<<<1, 1024>>>(W1, b1, w_syn, W2, b2);

    void* sp = nullptr;
    cudaGetSymbolAddress(&sp, g_stage);
    cudaMemcpyToSymbolAsync(c_P, sp, CP_SIZE * sizeof(float), 0,
                            cudaMemcpyDeviceToDevice, 0);

    const int spb = WARPS * SPW;
    const int blocks = (N + spb - 1) / spb;
    snn_kernel<<<blocks, WARPS * 32>>>(x, out, N);
}